// round 17
// baseline (speedup 1.0000x reference)
#include <cuda_runtime.h>
#include <cstdint>

// CNOT (13 qubits, control bit12, target bit11 of the state row) as a pure
// permutation copy: out[i,:] = x[i ^ ((i&4096)>>1), :]. U never read.
//
// Established (R6/R10/R15, rel_err=0): x = 524288 floats (64 per state row);
// at flat float4-index granularity src = idx ^ ((idx & swapbit4) >> 1).
//
// R15 ncu: kernel time flat (~4.3-4.9us) across 3 very different grids, DRAM
// ~6%, occ 11.9%. Model: short-burst kernel runs at low DVFS clock, cycles
// dominated by latency chain with only 8 warps/SM. This round: 1024-thread
// blocks -> 32 warps/SM, 128 CTAs (one wave), 1 float4 per thread (shortest
// dependent chain), identical 4MB traffic.

__global__ void __launch_bounds__(1024) cnot_perm_f4w(
    const float4* __restrict__ x, float4* __restrict__ out,
    int swapbit, int n4)
{
    int idx = blockIdx.x * blockDim.x + threadIdx.x;
    if (idx >= n4) return;
    out[idx] = x[idx ^ ((idx & swapbit) >> 1)];
}

__global__ void __launch_bounds__(256) cnot_perm_f1(
    const float* __restrict__ x, float* __restrict__ out,
    int swapbit, int n)
{
    int idx = blockIdx.x * blockDim.x + threadIdx.x;
    if (idx >= n) return;
    out[idx] = x[idx ^ ((idx & swapbit) >> 1)];
}

static constexpr int D_ROWS = 8192;

static inline int ilog2i(int v) { int s = 0; while ((1 << s) < v) s++; return s; }

extern "C" void kernel_launch(void* const* d_in, const int* in_sizes, int n_in,
                              void* d_out, int out_size)
{
    // x = smallest input buffer (U is ~128x larger under any lowering).
    int xi = 0;
    for (int i = 1; i < n_in; i++)
        if (in_sizes[i] < in_sizes[xi]) xi = i;

    int n = out_size < in_sizes[xi] ? out_size : in_sizes[xi];
    int fpr = n / D_ROWS;                 // floats per state row (R6: 64)
    if (fpr < 1) fpr = 1;
    int shift = ilog2i(fpr);
    n = D_ROWS << shift;                  // exact multiple of row count

    int swapbit_f = 4096 << shift;        // control bit in flat float index

    const float* xf = (const float*)d_in[xi];
    float* outf = (float*)d_out;

    bool aligned16 = ((((uintptr_t)xf) | ((uintptr_t)outf)) & 15) == 0;

    if ((n & 3) == 0 && shift >= 2 && aligned16) {
        int n4 = n >> 2;                              // 131072
        int swapbit4 = swapbit_f >> 2;                // same bit, f4 space
        constexpr int THREADS = 1024;
        int blocks = (n4 + THREADS - 1) / THREADS;    // 128
        cnot_perm_f4w<<<blocks, THREADS>>>((const float4*)xf, (float4*)outf,
                                           swapbit4, n4);
    } else {
        constexpr int THREADS = 256;
        int blocks = (n + THREADS - 1) / THREADS;
        cnot_perm_f1<<<blocks, THREADS>>>(xf, outf, swapbit_f, n);
    }
}